// round 15
// baseline (speedup 1.0000x reference)
#include <cuda_runtime.h>
#include <cuda_fp16.h>
#include <cstdint>

#define MAX_TOTAL 66560
#define MAX_B     2048
#define W_TOTAL   ((384 + 128) * 128)
#define W_WORDS   (W_TOTAL / 2)

__device__ uint32_t g_ctxP[(size_t)MAX_TOTAL * 64];    // attn out, fp16x2
__device__ int      g_off[MAX_B];
__device__ int      g_order[MAX_B];
__device__ uint32_t g_whP[W_WORDS];                    // packed fp16x2 W
__device__ uint32_t g_qP[(size_t)MAX_TOTAL * 64];      // Q/4 fp16x2, perm k
__device__ uint32_t g_kP[(size_t)MAX_TOTAL * 64];      // K fp16x2, perm k
__device__ uint32_t g_vP[(size_t)MAX_TOTAL * 64];      // V fp16x2, row-major

__device__ __forceinline__ uint32_t packh(float a, float b) {
    uint32_t r;
    asm("cvt.rn.f16x2.f32 %0, %1, %2;" : "=r"(r) : "f"(b), "f"(a));
    return r;   // lo = a, hi = b
}
// k-word interleave within an 8-word group: [0,4,1,5,2,6,3,7]
__device__ __forceinline__ int perm8(int j) {
    return (j & 4) ? (((j & 3) << 1) | 1) : (j << 1);
}

// ---------------------------------------------------------------------------
// Kernel 0 (merged): block 0 = offsets + descending-n order; blocks 1..128 =
// W1|W2 -> packed fp16 words.
// ---------------------------------------------------------------------------
__global__ void setup_kernel(const int* __restrict__ agents, int nB,
                             const float* __restrict__ w1,
                             const float* __restrict__ w2) {
    if (blockIdx.x == 0) {
        __shared__ int cnt[65];
        __shared__ int cur[65];
        if (threadIdx.x >= 32) return;
        const int lane = threadIdx.x;
        for (int i = lane; i < 65; i += 32) cnt[i] = 0;
        __syncwarp();

        const int base = lane * 64;
        int s = 0;
        for (int i = 0; i < 64; i++) {
            int idx = base + i;
            if (idx < nB) {
                int a = agents[idx];
                s += a;
                atomicAdd(&cnt[a], 1);
            }
        }
        int inc = s;
#pragma unroll
        for (int d = 1; d < 32; d <<= 1) {
            int v = __shfl_up_sync(0xffffffffu, inc, d);
            if (lane >= d) inc += v;
        }
        int run = inc - s;
        for (int i = 0; i < 64; i++) {
            int idx = base + i;
            if (idx < nB) {
                g_off[idx] = run;
                run += agents[idx];
            }
        }
        __syncwarp();
        if (lane == 0) {
            int acc = 0;
            for (int v = 64; v >= 1; v--) { cur[v] = acc; acc += cnt[v]; }
        }
        __syncwarp();
        for (int i = 0; i < 64; i++) {
            int idx = base + i;
            if (idx < nB) {
                int pos = atomicAdd(&cur[agents[idx]], 1);
                g_order[pos] = idx;
            }
        }
    } else {
        int i = (blockIdx.x - 1) * 256 + threadIdx.x;
        if (i >= W_WORDS) return;
        int j = 2 * i;
        float x0 = (j < 384 * 128) ? w1[j] : w2[j - 384 * 128];
        float x1 = (j + 1 < 384 * 128) ? w1[j + 1] : w2[j + 1 - 384 * 128];
        g_whP[i] = packh(x0, x1);
    }
}

// ---------------------------------------------------------------------------
// MMA wrapper
// ---------------------------------------------------------------------------
__device__ __forceinline__ void mma_f16(
    float* d, const uint32_t* a, uint32_t b0, uint32_t b1)
{
    asm volatile(
        "mma.sync.aligned.m16n8k16.row.col.f32.f16.f16.f32 "
        "{%0,%1,%2,%3}, {%4,%5,%6,%7}, {%8,%9}, {%0,%1,%2,%3};"
        : "+f"(d[0]), "+f"(d[1]), "+f"(d[2]), "+f"(d[3])
        : "r"(a[0]), "r"(a[1]), "r"(a[2]), "r"(a[3]), "r"(b0), "r"(b1));
}

#define GST 68
#define QKV_SMEM (3 * 128 * GST * 4)    // A + 2x B (ping-pong) = 104448 B
#define OUT_SMEM (2 * 128 * GST * 4)    // A + B = 69632 B

// ---------------------------------------------------------------------------
// Fused QKV projection, 1-term fp16, B double-buffered (1 sync per n-block).
//   Q out: fp16x2 scaled 0.25, permuted; K: fp16x2 permuted; V: fp16x2 plain.
// ---------------------------------------------------------------------------
__global__ __launch_bounds__(256, 2) void gemm_qkv_kernel(
    const float* __restrict__ X, const uint32_t* __restrict__ Wh,
    const float* __restrict__ bias,
    uint32_t* __restrict__ qP, uint32_t* __restrict__ kP,
    uint32_t* __restrict__ vP)
{
    extern __shared__ uint32_t sm[];
    uint32_t* Ah = sm;
    uint32_t* Bbuf = Ah + 128 * GST;   // two buffers of 128*GST

    const int tid = threadIdx.x;
    const int m_base = blockIdx.x * 128;
    const int warp = tid >> 5, lane = tid & 31;
    const int wm = warp & 3;
    const int wn = warp >> 2;
    const int g  = lane >> 2;
    const int t  = lane & 3;

    // ---- stage A once + B(0) into buf0 ----
#pragma unroll
    for (int i = 0; i < 16; i++) {
        int idx = tid + i * 256;
        int row = idx >> 5;
        int q   = idx & 31;
        float4 x = *(const float4*)(X + (size_t)(m_base + row) * 128 + q * 4);
        uint2 hv;
        hv.x = packh(x.x, x.y);
        hv.y = packh(x.z, x.w);
        *(uint2*)(Ah + row * GST + q * 2) = hv;
        uint2 wh = *(const uint2*)(Wh + (size_t)row * 64 + q * 2);
        *(uint2*)(Bbuf + row * GST + q * 2) = wh;
    }
    __syncthreads();

#pragma unroll
    for (int nb = 0; nb < 3; nb++) {
        uint32_t* Bcur = Bbuf + (nb & 1) * 128 * GST;
        uint32_t* Bnxt = Bbuf + ((nb + 1) & 1) * 128 * GST;

        // ---- prefetch next B while computing (different buffer) ----
        if (nb < 2) {
#pragma unroll
            for (int i = 0; i < 16; i++) {
                int idx = tid + i * 256;
                int row = idx >> 5;
                int q   = idx & 31;
                uint2 wh = *(const uint2*)(Wh + (size_t)((nb + 1) * 128 + row)
                                              * 64 + q * 2);
                *(uint2*)(Bnxt + row * GST + q * 2) = wh;
            }
        }

        float acc[2][8][4];
#pragma unroll
        for (int i = 0; i < 2; i++)
#pragma unroll
            for (int j = 0; j < 8; j++)
#pragma unroll
                for (int r = 0; r < 4; r++) acc[i][j][r] = 0.f;

#pragma unroll
        for (int ks = 0; ks < 8; ks++) {
            const int kw = ks * 8;
            uint32_t ah[2][4];
#pragma unroll
            for (int mt = 0; mt < 2; mt++) {
                int r0 = (wm * 32 + mt * 16 + g) * GST + kw;
                int r1 = r0 + 8 * GST;
                ah[mt][0] = Ah[r0 + t];     ah[mt][1] = Ah[r1 + t];
                ah[mt][2] = Ah[r0 + t + 4]; ah[mt][3] = Ah[r1 + t + 4];
            }
#pragma unroll
            for (int nt = 0; nt < 8; nt++) {
                int n0 = (wn * 64 + nt * 8 + g) * GST + kw;
                uint32_t bh0 = Bcur[n0 + t], bh1 = Bcur[n0 + t + 4];
#pragma unroll
                for (int mt = 0; mt < 2; mt++)
                    mma_f16(acc[mt][nt], ah[mt], bh0, bh1);
            }
        }

        // ---- epilogue (registers + gmem only; overlaps with staging) ----
        const float scale = (nb == 0) ? 0.25f : 1.f;
#pragma unroll
        for (int nt = 0; nt < 8; nt++) {
            int cn = wn * 64 + nt * 8 + 2 * t;
            float b0 = bias[nb * 128 + cn];
            float b1 = bias[nb * 128 + cn + 1];
#pragma unroll
            for (int mt = 0; mt < 2; mt++) {
                int rm = m_base + wm * 32 + mt * 16 + g;
                float v00 = acc[mt][nt][0] + b0, v01 = acc[mt][nt][1] + b1;
                float v10 = acc[mt][nt][2] + b0, v11 = acc[mt][nt][3] + b1;
                int wcol = cn >> 1;
                if (nb == 2) {
                    vP[(size_t)rm * 64 + wcol]       = packh(v00, v01);
                    vP[(size_t)(rm + 8) * 64 + wcol] = packh(v10, v11);
                } else {
                    uint32_t* dst = (nb == 0) ? qP : kP;
                    int wdst = (wcol & ~7) + perm8(wcol & 7);
                    dst[(size_t)rm * 64 + wdst] =
                        packh(v00 * scale, v01 * scale);
                    dst[(size_t)(rm + 8) * 64 + wdst] =
                        packh(v10 * scale, v11 * scale);
                }
            }
        }
        if (nb < 2) __syncthreads();
    }
}

// ---------------------------------------------------------------------------
// Out-projection GEMM: A pre-packed fp16 (ctxP) -> staging is a copy.
// ---------------------------------------------------------------------------
__global__ __launch_bounds__(256, 2) void gemm_out_kernel(
    const uint32_t* __restrict__ Xp, const uint32_t* __restrict__ Wh,
    const float* __restrict__ bias, float* __restrict__ C)
{
    extern __shared__ uint32_t sm[];
    uint32_t* Ah = sm;
    uint32_t* Bh = Ah + 128 * GST;

    const int tid = threadIdx.x;
    const int m_base = blockIdx.x * 128;
    const int warp = tid >> 5, lane = tid & 31;
    const int wm = warp & 3;
    const int wn = warp >> 2;
    const int g  = lane >> 2;
    const int t  = lane & 3;

#pragma unroll
    for (int i = 0; i < 16; i++) {
        int idx = tid + i * 256;
        int row = idx >> 5;
        int q   = idx & 31;
        uint2 hv = *(const uint2*)(Xp + (size_t)(m_base + row) * 64 + q * 2);
        *(uint2*)(Ah + row * GST + q * 2) = hv;
        uint2 wh = *(const uint2*)(Wh + (size_t)row * 64 + q * 2);
        *(uint2*)(Bh + row * GST + q * 2) = wh;
    }
    __syncthreads();

    float acc[2][8][4];
#pragma unroll
    for (int i = 0; i < 2; i++)
#pragma unroll
        for (int j = 0; j < 8; j++)
#pragma unroll
            for (int r = 0; r < 4; r++) acc[i][j][r] = 0.f;

#pragma unroll
    for (int ks = 0; ks < 8; ks++) {
        const int kw = ks * 8;
        uint32_t ah[2][4];
#pragma unroll
        for (int mt = 0; mt < 2; mt++) {
            int r0 = (wm * 32 + mt * 16 + g) * GST + kw;
            int r1 = r0 + 8 * GST;
            ah[mt][0] = Ah[r0 + t];     ah[mt][1] = Ah[r1 + t];
            ah[mt][2] = Ah[r0 + t + 4]; ah[mt][3] = Ah[r1 + t + 4];
        }
#pragma unroll
        for (int nt = 0; nt < 8; nt++) {
            int n0 = (wn * 64 + nt * 8 + g) * GST + kw;
            uint32_t bh0 = Bh[n0 + t], bh1 = Bh[n0 + t + 4];
#pragma unroll
            for (int mt = 0; mt < 2; mt++)
                mma_f16(acc[mt][nt], ah[mt], bh0, bh1);
        }
    }

#pragma unroll
    for (int nt = 0; nt < 8; nt++) {
        int cn = wn * 64 + nt * 8 + 2 * t;
        float b0 = bias[cn], b1 = bias[cn + 1];
#pragma unroll
        for (int mt = 0; mt < 2; mt++) {
            int rm = m_base + wm * 32 + mt * 16 + g;
            float2 v0 = {acc[mt][nt][0] + b0, acc[mt][nt][1] + b1};
            float2 v1 = {acc[mt][nt][2] + b0, acc[mt][nt][3] + b1};
            *(float2*)(C + (size_t)rm * 128 + cn) = v0;
            *(float2*)(C + (size_t)(rm + 8) * 128 + cn) = v1;
        }
    }
}

// ---------------------------------------------------------------------------
// Tensor-core ragged attention (direct-P fp16, mask-free):
//   K staging = permuted uint4 copy; V staging = fp16 uint2 + byte_perm
//   key-pairing (bit-identical to the old fp32->fp16 path).
// ---------------------------------------------------------------------------
#define KST 68
#define VAP 132
#define KPK_OFF  0
#define VPK_OFF  (64 * KST)                 // 4352
#define ATTN_SMEM ((VPK_OFF + 32 * VAP) * 4)   // 34304 B

__global__ __launch_bounds__(256, 4) void attn_mma_kernel(
    const uint32_t* __restrict__ qP, const uint32_t* __restrict__ kP,
    const uint32_t* __restrict__ vP, uint32_t* __restrict__ ctxP,
    const int* __restrict__ agents)
{
    extern __shared__ uint32_t smu[];
    uint32_t* Kpk = smu + KPK_OFF;
    uint32_t* Vpk = smu + VPK_OFF;

    const int b   = g_order[blockIdx.x];
    const int n   = agents[b];
    const int off = g_off[b];
    const int tid = threadIdx.x;
    const int npad = (n + 15) & ~15;

    // ---- stage K (straight permuted copy) ----
    for (int idx = tid; idx < npad * 16; idx += 256) {
        int r  = idx >> 4;
        int q4 = (idx & 15) * 4;
        uint4 kw = {0, 0, 0, 0};
        if (r < n)
            kw = *(const uint4*)(kP + (size_t)(off + r) * 64 + q4);
        *(uint4*)(Kpk + r * KST + q4) = kw;
    }

    // ---- stage V: fp16 rows -> key-pair words via byte_perm ----
    for (int idx = tid; idx < npad * 16; idx += 256) {
        int r2 = idx >> 5;                 // key-pair index
        int cw = (idx & 31) * 2;           // source word column (2 words)
        int r0 = 2 * r2, r1 = r0 + 1;
        uint2 a = {0, 0}, c = {0, 0};
        if (r0 < n) a = *(const uint2*)(vP + (size_t)(off + r0) * 64 + cw);
        if (r1 < n) c = *(const uint2*)(vP + (size_t)(off + r1) * 64 + cw);
        uint4 vp;
        vp.x = __byte_perm(a.x, c.x, 0x5410);
        vp.y = __byte_perm(a.x, c.x, 0x7632);
        vp.z = __byte_perm(a.y, c.y, 0x5410);
        vp.w = __byte_perm(a.y, c.y, 0x7632);
        *(uint4*)(Vpk + r2 * VAP + cw * 2) = vp;
    }
    __syncthreads();

    const int warp = tid >> 5;     // head
    const int lane = tid & 31;
    const int g = lane >> 2;
    const int t = lane & 3;
    const int h16 = warp * 16;
    const int h8  = warp * 8;

    const int nmt = (n + 15) >> 4;
    const float lfix = (float)(npad - n);

    for (int mt = 0; mt < nmt; mt++) {
        const int qr0 = min(mt * 16 + g, n - 1);
        const int qr1 = min(mt * 16 + 8 + g, n - 1);
        uint2 q0 = *(const uint2*)(qP + (size_t)(off + qr0) * 64 + h8 + 2 * t);
        uint2 q1 = *(const uint2*)(qP + (size_t)(off + qr1) * 64 + h8 + 2 * t);
        uint32_t qa[4];
        qa[0] = q0.x; qa[2] = q0.y;
        qa[1] = q1.x; qa[3] = q1.y;

        float oacc[2][4];
#pragma unroll
        for (int nt = 0; nt < 2; nt++)
#pragma unroll
            for (int r = 0; r < 4; r++) oacc[nt][r] = 0.f;
        float l0 = 0.f, l1 = 0.f;

        for (int kb = 0; kb < npad; kb += 16) {
            float sA[4] = {0,0,0,0}, sB[4] = {0,0,0,0};
            const uint32_t* kA = Kpk + (kb + g) * KST + h8;
            uint2 ka2 = *(const uint2*)(kA + 2 * t);
            uint2 kb2 = *(const uint2*)(kA + 8 * KST + 2 * t);
            mma_f16(sA, qa, ka2.x, ka2.y);
            mma_f16(sB, qa, kb2.x, kb2.y);

            float pA0 = __expf(sA[0]);
            float pA1 = __expf(sA[1]);
            float pA2 = __expf(sA[2]);
            float pA3 = __expf(sA[3]);
            float pB0 = __expf(sB[0]);
            float pB1 = __expf(sB[1]);
            float pB2 = __expf(sB[2]);
            float pB3 = __expf(sB[3]);
            l0 += (pA0 + pA1) + (pB0 + pB1);
            l1 += (pA2 + pA3) + (pB2 + pB3);

            uint32_t pa[4];
            pa[0] = packh(pA0, pA1);
            pa[1] = packh(pA2, pA3);
            pa[2] = packh(pB0, pB1);
            pa[3] = packh(pB2, pB3);

#pragma unroll
            for (int nt = 0; nt < 2; nt++) {
                const uint32_t* vp = Vpk + ((kb >> 1) + t) * VAP
                                         + h16 + nt * 8 + g;
                mma_f16(oacc[nt], pa, vp[0], vp[4 * VAP]);
            }
        }

        l0 += __shfl_xor_sync(0xffffffffu, l0, 1);
        l0 += __shfl_xor_sync(0xffffffffu, l0, 2);
        l1 += __shfl_xor_sync(0xffffffffu, l1, 1);
        l1 += __shfl_xor_sync(0xffffffffu, l1, 2);
        const float inv0 = 1.f / (l0 - lfix), inv1 = 1.f / (l1 - lfix);

        const int q0r = mt * 16 + g;
        const int q1r = q0r + 8;
#pragma unroll
        for (int nt = 0; nt < 2; nt++) {
            const int wcol = h8 + nt * 4 + t;
            if (q0r < n)
                ctxP[(size_t)(off + q0r) * 64 + wcol] =
                    packh(oacc[nt][0] * inv0, oacc[nt][1] * inv0);
            if (q1r < n)
                ctxP[(size_t)(off + q1r) * 64 + wcol] =
                    packh(oacc[nt][2] * inv1, oacc[nt][3] * inv1);
        }
    }
}

// ---------------------------------------------------------------------------
extern "C" void kernel_launch(void* const* d_in, const int* in_sizes, int n_in,
                              void* d_out, int out_size)
{
    const float* att_in = (const float*)d_in[0];
    const float* w1     = (const float*)d_in[1];
    const float* b1     = (const float*)d_in[2];
    const float* w2     = (const float*)d_in[3];
    const float* b2     = (const float*)d_in[4];
    const int*   agents = (const int*)d_in[5];

    const int M  = in_sizes[0] / 128;   // 66560
    const int nB = in_sizes[5];         // 2048

    uint32_t* whp = nullptr; uint32_t* ctxP = nullptr;
    uint32_t* qP = nullptr; uint32_t* kP = nullptr; uint32_t* vP = nullptr;
    cudaGetSymbolAddress((void**)&ctxP, g_ctxP);
    cudaGetSymbolAddress((void**)&whp, g_whP);
    cudaGetSymbolAddress((void**)&qP,  g_qP);
    cudaGetSymbolAddress((void**)&kP,  g_kP);
    cudaGetSymbolAddress((void**)&vP,  g_vP);

    cudaFuncSetAttribute(gemm_qkv_kernel,
                         cudaFuncAttributeMaxDynamicSharedMemorySize, QKV_SMEM);
    cudaFuncSetAttribute(gemm_out_kernel,
                         cudaFuncAttributeMaxDynamicSharedMemorySize, OUT_SMEM);
    cudaFuncSetAttribute(attn_mma_kernel,
                         cudaFuncAttributeMaxDynamicSharedMemorySize, ATTN_SMEM);

    setup_kernel<<<1 + (W_WORDS + 255) / 256, 256>>>(agents, nB, w1, w2);

    gemm_qkv_kernel<<<M / 128, 256, QKV_SMEM>>>(
        att_in, whp, b1, qP, kP, vP);

    attn_mma_kernel<<<nB, 256, ATTN_SMEM>>>(qP, kP, vP, ctxP, agents);

    gemm_out_kernel<<<M / 128, 256, OUT_SMEM>>>(
        ctxP, whp + 384 * 64, b2, (float*)d_out);
}

// round 16
// speedup vs baseline: 1.0629x; 1.0629x over previous
#include <cuda_runtime.h>
#include <cuda_fp16.h>
#include <cstdint>

#define MAX_TOTAL 66560
#define MAX_B     2048
#define W_TOTAL   ((384 + 128) * 128)
#define W_WORDS   (W_TOTAL / 2)

__device__ uint32_t g_ctxP[(size_t)MAX_TOTAL * 64];    // attn out, fp16x2
__device__ int      g_off[MAX_B];
__device__ int      g_order[MAX_B];
__device__ uint32_t g_whP[W_WORDS];                    // packed fp16x2 W
__device__ uint32_t g_qP[(size_t)MAX_TOTAL * 64];      // Q/4 fp16x2, perm k
__device__ uint32_t g_kP[(size_t)MAX_TOTAL * 64];      // K fp16x2, perm k
__device__ uint32_t g_vP[(size_t)MAX_TOTAL * 64];      // V fp16x2, row-major

__device__ __forceinline__ uint32_t packh(float a, float b) {
    uint32_t r;
    asm("cvt.rn.f16x2.f32 %0, %1, %2;" : "=r"(r) : "f"(b), "f"(a));
    return r;   // lo = a, hi = b
}
// k-word interleave within an 8-word group: [0,4,1,5,2,6,3,7]
__device__ __forceinline__ int perm8(int j) {
    return (j & 4) ? (((j & 3) << 1) | 1) : (j << 1);
}

// ---------------------------------------------------------------------------
// Kernel 0 (merged): block 0 (1024 thr) = parallel scan + counting-sort
// order; blocks 1.. = W1|W2 -> packed fp16 words.
// ---------------------------------------------------------------------------
__global__ void setup_kernel(const int* __restrict__ agents, int nB,
                             const float* __restrict__ w1,
                             const float* __restrict__ w2) {
    if (blockIdx.x == 0) {
        __shared__ int s[2][2048];
        __shared__ int av[2048];
        __shared__ int cnt[65];
        __shared__ int binoff[65];
        const int t = threadIdx.x;

        if (t < 65) cnt[t] = 0;
        for (int i = t; i < 2048; i += 1024) {
            int a = (i < nB) ? agents[i] : 0;
            av[i] = a;
            s[0][i] = a;
            if (i < nB) atomicAdd(&cnt[a], 1);
        }
        __syncthreads();

        // Hillis-Steele inclusive scan over 2048 elements
        int cur = 0;
        for (int off = 1; off < 2048; off <<= 1) {
            int nxt = cur ^ 1;
            for (int i = t; i < 2048; i += 1024) {
                int v = s[cur][i];
                if (i >= off) v += s[cur][i - off];
                s[nxt][i] = v;
            }
            __syncthreads();
            cur = nxt;
        }
        for (int i = t; i < 2048; i += 1024)
            if (i < nB) g_off[i] = s[cur][i] - av[i];

        // descending-n bin offsets (serial over 64 bins: trivial)
        if (t == 0) {
            int acc = 0;
            for (int v = 64; v >= 1; v--) { binoff[v] = acc; acc += cnt[v]; }
        }
        __syncthreads();
        for (int i = t; i < 2048; i += 1024) {
            if (i < nB) {
                int pos = atomicAdd(&binoff[av[i]], 1);
                g_order[pos] = i;
            }
        }
    } else {
        int i = (blockIdx.x - 1) * 1024 + threadIdx.x;
        if (i >= W_WORDS) return;
        int j = 2 * i;
        float x0 = (j < 384 * 128) ? w1[j] : w2[j - 384 * 128];
        float x1 = (j + 1 < 384 * 128) ? w1[j + 1] : w2[j + 1 - 384 * 128];
        g_whP[i] = packh(x0, x1);
    }
}

// ---------------------------------------------------------------------------
// MMA wrapper
// ---------------------------------------------------------------------------
__device__ __forceinline__ void mma_f16(
    float* d, const uint32_t* a, uint32_t b0, uint32_t b1)
{
    asm volatile(
        "mma.sync.aligned.m16n8k16.row.col.f32.f16.f16.f32 "
        "{%0,%1,%2,%3}, {%4,%5,%6,%7}, {%8,%9}, {%0,%1,%2,%3};"
        : "+f"(d[0]), "+f"(d[1]), "+f"(d[2]), "+f"(d[3])
        : "r"(a[0]), "r"(a[1]), "r"(a[2]), "r"(a[3]), "r"(b0), "r"(b1));
}

#define GST 68
#define GEMM_SMEM (2 * 128 * GST * 4)   // 69632 B (A + B single buffer)

// ---------------------------------------------------------------------------
// Fused QKV projection, 1-term fp16, single B buffer (R14 structure).
//   Q out: fp16x2 scaled 0.25, permuted; K: fp16x2 permuted; V: fp16x2 plain.
// ---------------------------------------------------------------------------
__global__ __launch_bounds__(256, 2) void gemm_qkv_kernel(
    const float* __restrict__ X, const uint32_t* __restrict__ Wh,
    const float* __restrict__ bias,
    uint32_t* __restrict__ qP, uint32_t* __restrict__ kP,
    uint32_t* __restrict__ vP)
{
    extern __shared__ uint32_t sm[];
    uint32_t* Ah = sm;
    uint32_t* Bh = Ah + 128 * GST;

    const int tid = threadIdx.x;
    const int m_base = blockIdx.x * 128;
    const int warp = tid >> 5, lane = tid & 31;
    const int wm = warp & 3;
    const int wn = warp >> 2;
    const int g  = lane >> 2;
    const int t  = lane & 3;

    // ---- stage A once ----
#pragma unroll
    for (int i = 0; i < 16; i++) {
        int idx = tid + i * 256;
        int row = idx >> 5;
        int q   = idx & 31;
        float4 x = *(const float4*)(X + (size_t)(m_base + row) * 128 + q * 4);
        uint2 hv;
        hv.x = packh(x.x, x.y);
        hv.y = packh(x.z, x.w);
        *(uint2*)(Ah + row * GST + q * 2) = hv;
    }

    for (int nb = 0; nb < 3; nb++) {
#pragma unroll
        for (int i = 0; i < 16; i++) {
            int idx = tid + i * 256;
            int row = idx >> 5;
            int q   = idx & 31;
            uint2 wh = *(const uint2*)(Wh + (size_t)(nb * 128 + row) * 64
                                          + q * 2);
            *(uint2*)(Bh + row * GST + q * 2) = wh;
        }
        __syncthreads();

        float acc[2][8][4];
#pragma unroll
        for (int i = 0; i < 2; i++)
#pragma unroll
            for (int j = 0; j < 8; j++)
#pragma unroll
                for (int r = 0; r < 4; r++) acc[i][j][r] = 0.f;

#pragma unroll
        for (int ks = 0; ks < 8; ks++) {
            const int kw = ks * 8;
            uint32_t ah[2][4];
#pragma unroll
            for (int mt = 0; mt < 2; mt++) {
                int r0 = (wm * 32 + mt * 16 + g) * GST + kw;
                int r1 = r0 + 8 * GST;
                ah[mt][0] = Ah[r0 + t];     ah[mt][1] = Ah[r1 + t];
                ah[mt][2] = Ah[r0 + t + 4]; ah[mt][3] = Ah[r1 + t + 4];
            }
#pragma unroll
            for (int nt = 0; nt < 8; nt++) {
                int n0 = (wn * 64 + nt * 8 + g) * GST + kw;
                uint32_t bh0 = Bh[n0 + t], bh1 = Bh[n0 + t + 4];
#pragma unroll
                for (int mt = 0; mt < 2; mt++)
                    mma_f16(acc[mt][nt], ah[mt], bh0, bh1);
            }
        }

        const float scale = (nb == 0) ? 0.25f : 1.f;
#pragma unroll
        for (int nt = 0; nt < 8; nt++) {
            int cn = wn * 64 + nt * 8 + 2 * t;
            float b0 = bias[nb * 128 + cn];
            float b1 = bias[nb * 128 + cn + 1];
#pragma unroll
            for (int mt = 0; mt < 2; mt++) {
                int rm = m_base + wm * 32 + mt * 16 + g;
                float v00 = acc[mt][nt][0] + b0, v01 = acc[mt][nt][1] + b1;
                float v10 = acc[mt][nt][2] + b0, v11 = acc[mt][nt][3] + b1;
                int wcol = cn >> 1;
                if (nb == 2) {
                    vP[(size_t)rm * 64 + wcol]       = packh(v00, v01);
                    vP[(size_t)(rm + 8) * 64 + wcol] = packh(v10, v11);
                } else {
                    uint32_t* dst = (nb == 0) ? qP : kP;
                    int wdst = (wcol & ~7) + perm8(wcol & 7);
                    dst[(size_t)rm * 64 + wdst] =
                        packh(v00 * scale, v01 * scale);
                    dst[(size_t)(rm + 8) * 64 + wdst] =
                        packh(v10 * scale, v11 * scale);
                }
            }
        }
        if (nb < 2) __syncthreads();
    }
}

// ---------------------------------------------------------------------------
// Out-projection GEMM: A pre-packed fp16 (ctxP) -> staging is a copy.
// ---------------------------------------------------------------------------
__global__ __launch_bounds__(256, 2) void gemm_out_kernel(
    const uint32_t* __restrict__ Xp, const uint32_t* __restrict__ Wh,
    const float* __restrict__ bias, float* __restrict__ C)
{
    extern __shared__ uint32_t sm[];
    uint32_t* Ah = sm;
    uint32_t* Bh = Ah + 128 * GST;

    const int tid = threadIdx.x;
    const int m_base = blockIdx.x * 128;
    const int warp = tid >> 5, lane = tid & 31;
    const int wm = warp & 3;
    const int wn = warp >> 2;
    const int g  = lane >> 2;
    const int t  = lane & 3;

#pragma unroll
    for (int i = 0; i < 16; i++) {
        int idx = tid + i * 256;
        int row = idx >> 5;
        int q   = idx & 31;
        uint2 hv = *(const uint2*)(Xp + (size_t)(m_base + row) * 64 + q * 2);
        *(uint2*)(Ah + row * GST + q * 2) = hv;
        uint2 wh = *(const uint2*)(Wh + (size_t)row * 64 + q * 2);
        *(uint2*)(Bh + row * GST + q * 2) = wh;
    }
    __syncthreads();

    float acc[2][8][4];
#pragma unroll
    for (int i = 0; i < 2; i++)
#pragma unroll
        for (int j = 0; j < 8; j++)
#pragma unroll
            for (int r = 0; r < 4; r++) acc[i][j][r] = 0.f;

#pragma unroll
    for (int ks = 0; ks < 8; ks++) {
        const int kw = ks * 8;
        uint32_t ah[2][4];
#pragma unroll
        for (int mt = 0; mt < 2; mt++) {
            int r0 = (wm * 32 + mt * 16 + g) * GST + kw;
            int r1 = r0 + 8 * GST;
            ah[mt][0] = Ah[r0 + t];     ah[mt][1] = Ah[r1 + t];
            ah[mt][2] = Ah[r0 + t + 4]; ah[mt][3] = Ah[r1 + t + 4];
        }
#pragma unroll
        for (int nt = 0; nt < 8; nt++) {
            int n0 = (wn * 64 + nt * 8 + g) * GST + kw;
            uint32_t bh0 = Bh[n0 + t], bh1 = Bh[n0 + t + 4];
#pragma unroll
            for (int mt = 0; mt < 2; mt++)
                mma_f16(acc[mt][nt], ah[mt], bh0, bh1);
        }
    }

#pragma unroll
    for (int nt = 0; nt < 8; nt++) {
        int cn = wn * 64 + nt * 8 + 2 * t;
        float b0 = bias[cn], b1 = bias[cn + 1];
#pragma unroll
        for (int mt = 0; mt < 2; mt++) {
            int rm = m_base + wm * 32 + mt * 16 + g;
            float2 v0 = {acc[mt][nt][0] + b0, acc[mt][nt][1] + b1};
            float2 v1 = {acc[mt][nt][2] + b0, acc[mt][nt][3] + b1};
            *(float2*)(C + (size_t)rm * 128 + cn) = v0;
            *(float2*)(C + (size_t)(rm + 8) * 128 + cn) = v1;
        }
    }
}

// ---------------------------------------------------------------------------
// Tensor-core ragged attention (direct-P fp16, mask-free; unchanged).
// ---------------------------------------------------------------------------
#define KST 68
#define VAP 132
#define KPK_OFF  0
#define VPK_OFF  (64 * KST)                 // 4352
#define ATTN_SMEM ((VPK_OFF + 32 * VAP) * 4)   // 34304 B

__global__ __launch_bounds__(256, 4) void attn_mma_kernel(
    const uint32_t* __restrict__ qP, const uint32_t* __restrict__ kP,
    const uint32_t* __restrict__ vP, uint32_t* __restrict__ ctxP,
    const int* __restrict__ agents)
{
    extern __shared__ uint32_t smu[];
    uint32_t* Kpk = smu + KPK_OFF;
    uint32_t* Vpk = smu + VPK_OFF;

    const int b   = g_order[blockIdx.x];
    const int n   = agents[b];
    const int off = g_off[b];
    const int tid = threadIdx.x;
    const int npad = (n + 15) & ~15;

    for (int idx = tid; idx < npad * 16; idx += 256) {
        int r  = idx >> 4;
        int q4 = (idx & 15) * 4;
        uint4 kw = {0, 0, 0, 0};
        if (r < n)
            kw = *(const uint4*)(kP + (size_t)(off + r) * 64 + q4);
        *(uint4*)(Kpk + r * KST + q4) = kw;
    }

    for (int idx = tid; idx < npad * 16; idx += 256) {
        int r2 = idx >> 5;
        int cw = (idx & 31) * 2;
        int r0 = 2 * r2, r1 = r0 + 1;
        uint2 a = {0, 0}, c = {0, 0};
        if (r0 < n) a = *(const uint2*)(vP + (size_t)(off + r0) * 64 + cw);
        if (r1 < n) c = *(const uint2*)(vP + (size_t)(off + r1) * 64 + cw);
        uint4 vp;
        vp.x = __byte_perm(a.x, c.x, 0x5410);
        vp.y = __byte_perm(a.x, c.x, 0x7632);
        vp.z = __byte_perm(a.y, c.y, 0x5410);
        vp.w = __byte_perm(a.y, c.y, 0x7632);
        *(uint4*)(Vpk + r2 * VAP + cw * 2) = vp;
    }
    __syncthreads();

    const int warp = tid >> 5;
    const int lane = tid & 31;
    const int g = lane >> 2;
    const int t = lane & 3;
    const int h16 = warp * 16;
    const int h8  = warp * 8;

    const int nmt = (n + 15) >> 4;
    const float lfix = (float)(npad - n);

    for (int mt = 0; mt < nmt; mt++) {
        const int qr0 = min(mt * 16 + g, n - 1);
        const int qr1 = min(mt * 16 + 8 + g, n - 1);
        uint2 q0 = *(const uint2*)(qP + (size_t)(off + qr0) * 64 + h8 + 2 * t);
        uint2 q1 = *(const uint2*)(qP + (size_t)(off + qr1) * 64 + h8 + 2 * t);
        uint32_t qa[4];
        qa[0] = q0.x; qa[2] = q0.y;
        qa[1] = q1.x; qa[3] = q1.y;

        float oacc[2][4];
#pragma unroll
        for (int nt = 0; nt < 2; nt++)
#pragma unroll
            for (int r = 0; r < 4; r++) oacc[nt][r] = 0.f;
        float l0 = 0.f, l1 = 0.f;

        for (int kb = 0; kb < npad; kb += 16) {
            float sA[4] = {0,0,0,0}, sB[4] = {0,0,0,0};
            const uint32_t* kA = Kpk + (kb + g) * KST + h8;
            uint2 ka2 = *(const uint2*)(kA + 2 * t);
            uint2 kb2 = *(const uint2*)(kA + 8 * KST + 2 * t);
            mma_f16(sA, qa, ka2.x, ka2.y);
            mma_f16(sB, qa, kb2.x, kb2.y);

            float pA0 = __expf(sA[0]);
            float pA1 = __expf(sA[1]);
            float pA2 = __expf(sA[2]);
            float pA3 = __expf(sA[3]);
            float pB0 = __expf(sB[0]);
            float pB1 = __expf(sB[1]);
            float pB2 = __expf(sB[2]);
            float pB3 = __expf(sB[3]);
            l0 += (pA0 + pA1) + (pB0 + pB1);
            l1 += (pA2 + pA3) + (pB2 + pB3);

            uint32_t pa[4];
            pa[0] = packh(pA0, pA1);
            pa[1] = packh(pA2, pA3);
            pa[2] = packh(pB0, pB1);
            pa[3] = packh(pB2, pB3);

#pragma unroll
            for (int nt = 0; nt < 2; nt++) {
                const uint32_t* vp = Vpk + ((kb >> 1) + t) * VAP
                                         + h16 + nt * 8 + g;
                mma_f16(oacc[nt], pa, vp[0], vp[4 * VAP]);
            }
        }

        l0 += __shfl_xor_sync(0xffffffffu, l0, 1);
        l0 += __shfl_xor_sync(0xffffffffu, l0, 2);
        l1 += __shfl_xor_sync(0xffffffffu, l1, 1);
        l1 += __shfl_xor_sync(0xffffffffu, l1, 2);
        const float inv0 = 1.f / (l0 - lfix), inv1 = 1.f / (l1 - lfix);

        const int q0r = mt * 16 + g;
        const int q1r = q0r + 8;
#pragma unroll
        for (int nt = 0; nt < 2; nt++) {
            const int wcol = h8 + nt * 4 + t;
            if (q0r < n)
                ctxP[(size_t)(off + q0r) * 64 + wcol] =
                    packh(oacc[nt][0] * inv0, oacc[nt][1] * inv0);
            if (q1r < n)
                ctxP[(size_t)(off + q1r) * 64 + wcol] =
                    packh(oacc[nt][2] * inv1, oacc[nt][3] * inv1);
        }
    }
}

// ---------------------------------------------------------------------------
extern "C" void kernel_launch(void* const* d_in, const int* in_sizes, int n_in,
                              void* d_out, int out_size)
{
    const float* att_in = (const float*)d_in[0];
    const float* w1     = (const float*)d_in[1];
    const float* b1     = (const float*)d_in[2];
    const float* w2     = (const float*)d_in[3];
    const float* b2     = (const float*)d_in[4];
    const int*   agents = (const int*)d_in[5];

    const int M  = in_sizes[0] / 128;   // 66560
    const int nB = in_sizes[5];         // 2048

    uint32_t* whp = nullptr; uint32_t* ctxP = nullptr;
    uint32_t* qP = nullptr; uint32_t* kP = nullptr; uint32_t* vP = nullptr;
    cudaGetSymbolAddress((void**)&ctxP, g_ctxP);
    cudaGetSymbolAddress((void**)&whp, g_whP);
    cudaGetSymbolAddress((void**)&qP,  g_qP);
    cudaGetSymbolAddress((void**)&kP,  g_kP);
    cudaGetSymbolAddress((void**)&vP,  g_vP);

    cudaFuncSetAttribute(gemm_qkv_kernel,
                         cudaFuncAttributeMaxDynamicSharedMemorySize, GEMM_SMEM);
    cudaFuncSetAttribute(gemm_out_kernel,
                         cudaFuncAttributeMaxDynamicSharedMemorySize, GEMM_SMEM);
    cudaFuncSetAttribute(attn_mma_kernel,
                         cudaFuncAttributeMaxDynamicSharedMemorySize, ATTN_SMEM);

    setup_kernel<<<1 + (W_WORDS + 1023) / 1024, 1024>>>(agents, nB, w1, w2);

    gemm_qkv_kernel<<<M / 128, 256, GEMM_SMEM>>>(
        att_in, whp, b1, qP, kP, vP);

    attn_mma_kernel<<<nB, 256, ATTN_SMEM>>>(qP, kP, vP, ctxP, agents);

    gemm_out_kernel<<<M / 128, 256, GEMM_SMEM>>>(
        ctxP, whp + 384 * 64, b2, (float*)d_out);
}

// round 17
// speedup vs baseline: 1.2280x; 1.1553x over previous
#include <cuda_runtime.h>
#include <cuda_fp16.h>
#include <cstdint>

#define MAX_TOTAL 66560
#define MAX_B     2048
#define W_TOTAL   ((384 + 128) * 128)
#define W_WORDS   (W_TOTAL / 2)

__device__ uint32_t g_ctxP[(size_t)MAX_TOTAL * 64];    // attn out, fp16x2
__device__ int      g_off[MAX_B];
__device__ int      g_order[MAX_B];
__device__ uint32_t g_whP[W_WORDS];                    // packed fp16x2 W
__device__ uint32_t g_qP[(size_t)MAX_TOTAL * 64];      // Q/4 fp16x2, perm k
__device__ uint32_t g_kP[(size_t)MAX_TOTAL * 64];      // K fp16x2, perm k
__device__ uint32_t g_vP[(size_t)MAX_TOTAL * 64];      // V fp16x2, row-major

__device__ __forceinline__ uint32_t packh(float a, float b) {
    uint32_t r;
    asm("cvt.rn.f16x2.f32 %0, %1, %2;" : "=r"(r) : "f"(b), "f"(a));
    return r;   // lo = a, hi = b
}
// k-word interleave within an 8-word group: [0,4,1,5,2,6,3,7]
__device__ __forceinline__ int perm8(int j) {
    return (j & 4) ? (((j & 3) << 1) | 1) : (j << 1);
}

// ---------------------------------------------------------------------------
// Kernel 0 (merged): block 0 (1024 thr) = parallel scan + counting-sort
// order; blocks 1.. = W1|W2 -> packed fp16 words.
// ---------------------------------------------------------------------------
__global__ void setup_kernel(const int* __restrict__ agents, int nB,
                             const float* __restrict__ w1,
                             const float* __restrict__ w2) {
    if (blockIdx.x == 0) {
        __shared__ int s[2][2048];
        __shared__ int av[2048];
        __shared__ int cnt[65];
        __shared__ int binoff[65];
        const int t = threadIdx.x;

        if (t < 65) cnt[t] = 0;
        for (int i = t; i < 2048; i += 1024) {
            int a = (i < nB) ? agents[i] : 0;
            av[i] = a;
            s[0][i] = a;
            if (i < nB) atomicAdd(&cnt[a], 1);
        }
        __syncthreads();

        int cur = 0;
        for (int off = 1; off < 2048; off <<= 1) {
            int nxt = cur ^ 1;
            for (int i = t; i < 2048; i += 1024) {
                int v = s[cur][i];
                if (i >= off) v += s[cur][i - off];
                s[nxt][i] = v;
            }
            __syncthreads();
            cur = nxt;
        }
        for (int i = t; i < 2048; i += 1024)
            if (i < nB) g_off[i] = s[cur][i] - av[i];

        if (t == 0) {
            int acc = 0;
            for (int v = 64; v >= 1; v--) { binoff[v] = acc; acc += cnt[v]; }
        }
        __syncthreads();
        for (int i = t; i < 2048; i += 1024) {
            if (i < nB) {
                int pos = atomicAdd(&binoff[av[i]], 1);
                g_order[pos] = i;
            }
        }
    } else {
        int i = (blockIdx.x - 1) * 1024 + threadIdx.x;
        if (i >= W_WORDS) return;
        int j = 2 * i;
        float x0 = (j < 384 * 128) ? w1[j] : w2[j - 384 * 128];
        float x1 = (j + 1 < 384 * 128) ? w1[j + 1] : w2[j + 1 - 384 * 128];
        g_whP[i] = packh(x0, x1);
    }
}

// ---------------------------------------------------------------------------
// MMA wrapper
// ---------------------------------------------------------------------------
__device__ __forceinline__ void mma_f16(
    float* d, const uint32_t* a, uint32_t b0, uint32_t b1)
{
    asm volatile(
        "mma.sync.aligned.m16n8k16.row.col.f32.f16.f16.f32 "
        "{%0,%1,%2,%3}, {%4,%5,%6,%7}, {%8,%9}, {%0,%1,%2,%3};"
        : "+f"(d[0]), "+f"(d[1]), "+f"(d[2]), "+f"(d[3])
        : "r"(a[0]), "r"(a[1]), "r"(a[2]), "r"(a[3]), "r"(b0), "r"(b1));
}

#define GST 68
// A: 128 rows, B: 64 rows (n-chunk)
#define GEMM_SMEM ((128 * GST + 64 * GST) * 4)   // 52224 B

// ---------------------------------------------------------------------------
// Fused QKV projection: 32m x 32n warptile (acc 32 regs, 3 CTAs/SM).
//   A (fp16 of X) staged once; 6 n-chunks of 64 over [Wq|Wk|Wv].
// ---------------------------------------------------------------------------
__global__ __launch_bounds__(256, 3) void gemm_qkv_kernel(
    const float* __restrict__ X, const uint32_t* __restrict__ Wh,
    const float* __restrict__ bias,
    uint32_t* __restrict__ qP, uint32_t* __restrict__ kP,
    uint32_t* __restrict__ vP)
{
    extern __shared__ uint32_t sm[];
    uint32_t* Ah = sm;
    uint32_t* Bh = Ah + 128 * GST;

    const int tid = threadIdx.x;
    const int m_base = blockIdx.x * 128;
    const int warp = tid >> 5, lane = tid & 31;
    const int wm = warp & 3;        // m quadrant (32 rows)
    const int wn = warp >> 2;       // n half within chunk (32 cols)
    const int g  = lane >> 2;
    const int t  = lane & 3;

    // ---- stage A once ----
#pragma unroll
    for (int i = 0; i < 16; i++) {
        int idx = tid + i * 256;
        int row = idx >> 5;
        int q   = idx & 31;
        float4 x = *(const float4*)(X + (size_t)(m_base + row) * 128 + q * 4);
        uint2 hv;
        hv.x = packh(x.x, x.y);
        hv.y = packh(x.z, x.w);
        *(uint2*)(Ah + row * GST + q * 2) = hv;
    }

    for (int c = 0; c < 6; c++) {
        // ---- stage B chunk: W rows [c*64, c*64+64) ----
#pragma unroll
        for (int i = 0; i < 8; i++) {
            int idx = tid + i * 256;
            int row = idx >> 5;          // 0..63
            int q   = idx & 31;
            uint2 wh = *(const uint2*)(Wh + (size_t)(c * 64 + row) * 64
                                          + q * 2);
            *(uint2*)(Bh + row * GST + q * 2) = wh;
        }
        __syncthreads();

        float acc[2][4][4];
#pragma unroll
        for (int i = 0; i < 2; i++)
#pragma unroll
            for (int j = 0; j < 4; j++)
#pragma unroll
                for (int r = 0; r < 4; r++) acc[i][j][r] = 0.f;

#pragma unroll
        for (int ks = 0; ks < 8; ks++) {
            const int kw = ks * 8;
            uint32_t ah[2][4];
#pragma unroll
            for (int mt = 0; mt < 2; mt++) {
                int r0 = (wm * 32 + mt * 16 + g) * GST + kw;
                int r1 = r0 + 8 * GST;
                ah[mt][0] = Ah[r0 + t];     ah[mt][1] = Ah[r1 + t];
                ah[mt][2] = Ah[r0 + t + 4]; ah[mt][3] = Ah[r1 + t + 4];
            }
#pragma unroll
            for (int nt = 0; nt < 4; nt++) {
                int n0 = (wn * 32 + nt * 8 + g) * GST + kw;
                uint32_t bh0 = Bh[n0 + t], bh1 = Bh[n0 + t + 4];
#pragma unroll
                for (int mt = 0; mt < 2; mt++)
                    mma_f16(acc[mt][nt], ah[mt], bh0, bh1);
            }
        }

        // ---- epilogue: chunk c -> matrix (c>>1), n offset (c&1)*64 ----
        const int mat = c >> 1;
        const float scale = (mat == 0) ? 0.25f : 1.f;
#pragma unroll
        for (int nt = 0; nt < 4; nt++) {
            int cn = (c & 1) * 64 + wn * 32 + nt * 8 + 2 * t;   // 0..127
            float b0 = bias[mat * 128 + cn];
            float b1 = bias[mat * 128 + cn + 1];
#pragma unroll
            for (int mt = 0; mt < 2; mt++) {
                int rm = m_base + wm * 32 + mt * 16 + g;
                float v00 = acc[mt][nt][0] + b0, v01 = acc[mt][nt][1] + b1;
                float v10 = acc[mt][nt][2] + b0, v11 = acc[mt][nt][3] + b1;
                int wcol = cn >> 1;
                if (mat == 2) {
                    vP[(size_t)rm * 64 + wcol]       = packh(v00, v01);
                    vP[(size_t)(rm + 8) * 64 + wcol] = packh(v10, v11);
                } else {
                    uint32_t* dst = (mat == 0) ? qP : kP;
                    int wdst = (wcol & ~7) + perm8(wcol & 7);
                    dst[(size_t)rm * 64 + wdst] =
                        packh(v00 * scale, v01 * scale);
                    dst[(size_t)(rm + 8) * 64 + wdst] =
                        packh(v10 * scale, v11 * scale);
                }
            }
        }
        if (c < 5) __syncthreads();
    }
}

// ---------------------------------------------------------------------------
// Out-projection GEMM: 32m x 32n warptile, grid = (M/128)*2, bx&1 = n-half
// (adjacent blocks share the A tile -> L1/L2 reuse). A pre-packed fp16.
// ---------------------------------------------------------------------------
__global__ __launch_bounds__(256, 3) void gemm_out_kernel(
    const uint32_t* __restrict__ Xp, const uint32_t* __restrict__ Wh,
    const float* __restrict__ bias, float* __restrict__ C)
{
    extern __shared__ uint32_t sm[];
    uint32_t* Ah = sm;
    uint32_t* Bh = Ah + 128 * GST;

    const int tid = threadIdx.x;
    const int m_base = (blockIdx.x >> 1) * 128;
    const int n_base = (blockIdx.x & 1) * 64;
    const int warp = tid >> 5, lane = tid & 31;
    const int wm = warp & 3;
    const int wn = warp >> 2;
    const int g  = lane >> 2;
    const int t  = lane & 3;

#pragma unroll
    for (int i = 0; i < 16; i++) {
        int idx = tid + i * 256;
        int row = idx >> 5;
        int q   = idx & 31;
        uint2 hv = *(const uint2*)(Xp + (size_t)(m_base + row) * 64 + q * 2);
        *(uint2*)(Ah + row * GST + q * 2) = hv;
    }
#pragma unroll
    for (int i = 0; i < 8; i++) {
        int idx = tid + i * 256;
        int row = idx >> 5;          // 0..63
        int q   = idx & 31;
        uint2 wh = *(const uint2*)(Wh + (size_t)(n_base + row) * 64 + q * 2);
        *(uint2*)(Bh + row * GST + q * 2) = wh;
    }
    __syncthreads();

    float acc[2][4][4];
#pragma unroll
    for (int i = 0; i < 2; i++)
#pragma unroll
        for (int j = 0; j < 4; j++)
#pragma unroll
            for (int r = 0; r < 4; r++) acc[i][j][r] = 0.f;

#pragma unroll
    for (int ks = 0; ks < 8; ks++) {
        const int kw = ks * 8;
        uint32_t ah[2][4];
#pragma unroll
        for (int mt = 0; mt < 2; mt++) {
            int r0 = (wm * 32 + mt * 16 + g) * GST + kw;
            int r1 = r0 + 8 * GST;
            ah[mt][0] = Ah[r0 + t];     ah[mt][1] = Ah[r1 + t];
            ah[mt][2] = Ah[r0 + t + 4]; ah[mt][3] = Ah[r1 + t + 4];
        }
#pragma unroll
        for (int nt = 0; nt < 4; nt++) {
            int n0 = (wn * 32 + nt * 8 + g) * GST + kw;
            uint32_t bh0 = Bh[n0 + t], bh1 = Bh[n0 + t + 4];
#pragma unroll
            for (int mt = 0; mt < 2; mt++)
                mma_f16(acc[mt][nt], ah[mt], bh0, bh1);
        }
    }

#pragma unroll
    for (int nt = 0; nt < 4; nt++) {
        int cn = n_base + wn * 32 + nt * 8 + 2 * t;
        float b0 = bias[cn], b1 = bias[cn + 1];
#pragma unroll
        for (int mt = 0; mt < 2; mt++) {
            int rm = m_base + wm * 32 + mt * 16 + g;
            float2 v0 = {acc[mt][nt][0] + b0, acc[mt][nt][1] + b1};
            float2 v1 = {acc[mt][nt][2] + b0, acc[mt][nt][3] + b1};
            *(float2*)(C + (size_t)rm * 128 + cn) = v0;
            *(float2*)(C + (size_t)(rm + 8) * 128 + cn) = v1;
        }
    }
}

// ---------------------------------------------------------------------------
// Tensor-core ragged attention (direct-P fp16, mask-free; unchanged).
// ---------------------------------------------------------------------------
#define KST 68
#define VAP 132
#define KPK_OFF  0
#define VPK_OFF  (64 * KST)                 // 4352
#define ATTN_SMEM ((VPK_OFF + 32 * VAP) * 4)   // 34304 B

__global__ __launch_bounds__(256, 4) void attn_mma_kernel(
    const uint32_t* __restrict__ qP, const uint32_t* __restrict__ kP,
    const uint32_t* __restrict__ vP, uint32_t* __restrict__ ctxP,
    const int* __restrict__ agents)
{
    extern __shared__ uint32_t smu[];
    uint32_t* Kpk = smu + KPK_OFF;
    uint32_t* Vpk = smu + VPK_OFF;

    const int b   = g_order[blockIdx.x];
    const int n   = agents[b];
    const int off = g_off[b];
    const int tid = threadIdx.x;
    const int npad = (n + 15) & ~15;

    for (int idx = tid; idx < npad * 16; idx += 256) {
        int r  = idx >> 4;
        int q4 = (idx & 15) * 4;
        uint4 kw = {0, 0, 0, 0};
        if (r < n)
            kw = *(const uint4*)(kP + (size_t)(off + r) * 64 + q4);
        *(uint4*)(Kpk + r * KST + q4) = kw;
    }

    for (int idx = tid; idx < npad * 16; idx += 256) {
        int r2 = idx >> 5;
        int cw = (idx & 31) * 2;
        int r0 = 2 * r2, r1 = r0 + 1;
        uint2 a = {0, 0}, c = {0, 0};
        if (r0 < n) a = *(const uint2*)(vP + (size_t)(off + r0) * 64 + cw);
        if (r1 < n) c = *(const uint2*)(vP + (size_t)(off + r1) * 64 + cw);
        uint4 vp;
        vp.x = __byte_perm(a.x, c.x, 0x5410);
        vp.y = __byte_perm(a.x, c.x, 0x7632);
        vp.z = __byte_perm(a.y, c.y, 0x5410);
        vp.w = __byte_perm(a.y, c.y, 0x7632);
        *(uint4*)(Vpk + r2 * VAP + cw * 2) = vp;
    }
    __syncthreads();

    const int warp = tid >> 5;
    const int lane = tid & 31;
    const int g = lane >> 2;
    const int t = lane & 3;
    const int h16 = warp * 16;
    const int h8  = warp * 8;

    const int nmt = (n + 15) >> 4;
    const float lfix = (float)(npad - n);

    for (int mt = 0; mt < nmt; mt++) {
        const int qr0 = min(mt * 16 + g, n - 1);
        const int qr1 = min(mt * 16 + 8 + g, n - 1);
        uint2 q0 = *(const uint2*)(qP + (size_t)(off + qr0) * 64 + h8 + 2 * t);
        uint2 q1 = *(const uint2*)(qP + (size_t)(off + qr1) * 64 + h8 + 2 * t);
        uint32_t qa[4];
        qa[0] = q0.x; qa[2] = q0.y;
        qa[1] = q1.x; qa[3] = q1.y;

        float oacc[2][4];
#pragma unroll
        for (int nt = 0; nt < 2; nt++)
#pragma unroll
            for (int r = 0; r < 4; r++) oacc[nt][r] = 0.f;
        float l0 = 0.f, l1 = 0.f;

        for (int kb = 0; kb < npad; kb += 16) {
            float sA[4] = {0,0,0,0}, sB[4] = {0,0,0,0};
            const uint32_t* kA = Kpk + (kb + g) * KST + h8;
            uint2 ka2 = *(const uint2*)(kA + 2 * t);
            uint2 kb2 = *(const uint2*)(kA + 8 * KST + 2 * t);
            mma_f16(sA, qa, ka2.x, ka2.y);
            mma_f16(sB, qa, kb2.x, kb2.y);

            float pA0 = __expf(sA[0]);
            float pA1 = __expf(sA[1]);
            float pA2 = __expf(sA[2]);
            float pA3 = __expf(sA[3]);
            float pB0 = __expf(sB[0]);
            float pB1 = __expf(sB[1]);
            float pB2 = __expf(sB[2]);
            float pB3 = __expf(sB[3]);
            l0 += (pA0 + pA1) + (pB0 + pB1);
            l1 += (pA2 + pA3) + (pB2 + pB3);

            uint32_t pa[4];
            pa[0] = packh(pA0, pA1);
            pa[1] = packh(pA2, pA3);
            pa[2] = packh(pB0, pB1);
            pa[3] = packh(pB2, pB3);

#pragma unroll
            for (int nt = 0; nt < 2; nt++) {
                const uint32_t* vp = Vpk + ((kb >> 1) + t) * VAP
                                         + h16 + nt * 8 + g;
                mma_f16(oacc[nt], pa, vp[0], vp[4 * VAP]);
            }
        }

        l0 += __shfl_xor_sync(0xffffffffu, l0, 1);
        l0 += __shfl_xor_sync(0xffffffffu, l0, 2);
        l1 += __shfl_xor_sync(0xffffffffu, l1, 1);
        l1 += __shfl_xor_sync(0xffffffffu, l1, 2);
        const float inv0 = 1.f / (l0 - lfix), inv1 = 1.f / (l1 - lfix);

        const int q0r = mt * 16 + g;
        const int q1r = q0r + 8;
#pragma unroll
        for (int nt = 0; nt < 2; nt++) {
            const int wcol = h8 + nt * 4 + t;
            if (q0r < n)
                ctxP[(size_t)(off + q0r) * 64 + wcol] =
                    packh(oacc[nt][0] * inv0, oacc[nt][1] * inv0);
            if (q1r < n)
                ctxP[(size_t)(off + q1r) * 64 + wcol] =
                    packh(oacc[nt][2] * inv1, oacc[nt][3] * inv1);
        }
    }
}

// ---------------------------------------------------------------------------
extern "C" void kernel_launch(void* const* d_in, const int* in_sizes, int n_in,
                              void* d_out, int out_size)
{
    const float* att_in = (const float*)d_in[0];
    const float* w1     = (const float*)d_in[1];
    const float* b1     = (const float*)d_in[2];
    const float* w2     = (const float*)d_in[3];
    const float* b2     = (const float*)d_in[4];
    const int*   agents = (const int*)d_in[5];

    const int M  = in_sizes[0] / 128;   // 66560
    const int nB = in_sizes[5];         // 2048

    uint32_t* whp = nullptr; uint32_t* ctxP = nullptr;
    uint32_t* qP = nullptr; uint32_t* kP = nullptr; uint32_t* vP = nullptr;
    cudaGetSymbolAddress((void**)&ctxP, g_ctxP);
    cudaGetSymbolAddress((void**)&whp, g_whP);
    cudaGetSymbolAddress((void**)&qP,  g_qP);
    cudaGetSymbolAddress((void**)&kP,  g_kP);
    cudaGetSymbolAddress((void**)&vP,  g_vP);

    cudaFuncSetAttribute(gemm_qkv_kernel,
                         cudaFuncAttributeMaxDynamicSharedMemorySize, GEMM_SMEM);
    cudaFuncSetAttribute(gemm_out_kernel,
                         cudaFuncAttributeMaxDynamicSharedMemorySize, GEMM_SMEM);
    cudaFuncSetAttribute(attn_mma_kernel,
                         cudaFuncAttributeMaxDynamicSharedMemorySize, ATTN_SMEM);

    setup_kernel<<<1 + (W_WORDS + 1023) / 1024, 1024>>>(agents, nB, w1, w2);

    gemm_qkv_kernel<<<M / 128, 256, GEMM_SMEM>>>(
        att_in, whp, b1, qP, kP, vP);

    attn_mma_kernel<<<nB, 256, ATTN_SMEM>>>(qP, kP, vP, ctxP, agents);

    gemm_out_kernel<<<(M / 128) * 2, 256, GEMM_SMEM>>>(
        ctxP, whp + 384 * 64, b2, (float*)d_out);
}